// round 10
// baseline (speedup 1.0000x reference)
#include <cuda_runtime.h>
#include <cuda_bf16.h>
#include <math.h>
#include <stdint.h>

#define Tn   4096
#define Dm   1024
#define Hm   4096
#define NE   8
#define CAP  1280
#define LDA  40          // A smem row stride (halfs), 16B-aligned rows
#define LDB  136         // B smem row stride (halfs), 16B-aligned rows
#define AH_  0
#define AL_  5120        // 128*40
#define BH_  10240
#define BL_  14592       // 10240 + 32*136
#define SMH  18944       // total halfs (37888 B, fits static 48K)

typedef unsigned int u32;
typedef unsigned short u16;

// ---------------- device scratch ----------------
__device__ int   g_e0[Tn], g_e1[Tn];
__device__ float g_w0[Tn], g_w1[Tn];
__device__ int   g_s0[Tn], g_s1[Tn];
__device__ int   g_tok[NE * CAP];
__device__ int   g_count[NE];
__device__ float g_h [(size_t)NE * CAP * Hm];
__device__ float g_eo[(size_t)NE * CAP * Dm];

// ---------------- helpers ----------------
__device__ __forceinline__ u32 smem_u32(const void* p) {
    u32 a;
    asm("{ .reg .u64 t; cvta.to.shared.u64 t, %1; cvt.u32.u64 %0, t; }" : "=r"(a) : "l"(p));
    return a;
}
__device__ __forceinline__ void ldsm4(u32* r, u32 a) {
    asm volatile("ldmatrix.sync.aligned.m8n8.x4.shared.b16 {%0,%1,%2,%3}, [%4];"
                 : "=r"(r[0]), "=r"(r[1]), "=r"(r[2]), "=r"(r[3]) : "r"(a));
}
__device__ __forceinline__ void ldsm4t(u32* r, u32 a) {
    asm volatile("ldmatrix.sync.aligned.m8n8.x4.trans.shared.b16 {%0,%1,%2,%3}, [%4];"
                 : "=r"(r[0]), "=r"(r[1]), "=r"(r[2]), "=r"(r[3]) : "r"(a));
}
__device__ __forceinline__ void mma16816(float* d, const u32* a, u32 b0, u32 b1) {
    asm volatile(
        "mma.sync.aligned.m16n8k16.row.col.f32.bf16.bf16.f32 "
        "{%0,%1,%2,%3}, {%4,%5,%6,%7}, {%8,%9}, {%0,%1,%2,%3};"
        : "+f"(d[0]), "+f"(d[1]), "+f"(d[2]), "+f"(d[3])
        : "r"(a[0]), "r"(a[1]), "r"(a[2]), "r"(a[3]), "r"(b0), "r"(b1));
}
__device__ __forceinline__ u32 pack2bf(__nv_bfloat16 a, __nv_bfloat16 b) {
    __nv_bfloat162 t; t.x = a; t.y = b;
    return *reinterpret_cast<u32*>(&t);
}

// ---------------- router (verbatim, passing) ----------------
__global__ void router_kernel(const float* __restrict__ x, const float* __restrict__ wg) {
    int warp = (blockIdx.x * blockDim.x + threadIdx.x) >> 5;
    int lane = threadIdx.x & 31;
    if (warp >= Tn) return;
    const float4* x4 = (const float4*)(x + (size_t)warp * Dm);
    float acc[NE];
#pragma unroll
    for (int e = 0; e < NE; e++) acc[e] = 0.f;
#pragma unroll
    for (int i = 0; i < Dm / 128; i++) {
        float4 v = x4[lane + i * 32];
        int k0 = (lane + i * 32) * 4;
#pragma unroll
        for (int j = 0; j < 4; j++) {
            float xv = (j == 0) ? v.x : (j == 1) ? v.y : (j == 2) ? v.z : v.w;
            float4 wA = *(const float4*)(wg + (size_t)(k0 + j) * NE);
            float4 wB = *(const float4*)(wg + (size_t)(k0 + j) * NE + 4);
            acc[0] += xv * wA.x; acc[1] += xv * wA.y; acc[2] += xv * wA.z; acc[3] += xv * wA.w;
            acc[4] += xv * wB.x; acc[5] += xv * wB.y; acc[6] += xv * wB.z; acc[7] += xv * wB.w;
        }
    }
#pragma unroll
    for (int off = 16; off; off >>= 1)
#pragma unroll
        for (int e = 0; e < NE; e++) acc[e] += __shfl_xor_sync(0xffffffffu, acc[e], off);
    if (lane == 0) {
        int b0 = 0; float v0 = acc[0];
        for (int e = 1; e < NE; e++) if (acc[e] > v0) { v0 = acc[e]; b0 = e; }
        int b1 = -1; float v1 = -INFINITY;
        for (int e = 0; e < NE; e++) if (e != b0 && acc[e] > v1) { v1 = acc[e]; b1 = e; }
        float e1 = expf(v1 - v0);
        float inv = 1.0f / (1.0f + e1);
        g_e0[warp] = b0; g_e1[warp] = b1;
        g_w0[warp] = inv; g_w1[warp] = e1 * inv;
    }
}

// ---------------- assignment (verbatim, passing) ----------------
__global__ void assign_kernel() {
    int e = threadIdx.x >> 5, lane = threadIdx.x & 31;
    int base = 0;
    for (int i0 = 0; i0 < 2 * Tn; i0 += 32) {
        int idx = i0 + lane;
        int t = idx & (Tn - 1);
        int sel = (idx < Tn) ? g_e0[t] : g_e1[t];
        bool mine = (sel == e);
        unsigned bal = __ballot_sync(0xffffffffu, mine);
        int pre = __popc(bal & ((1u << lane) - 1u));
        if (mine) {
            int slot = base + pre;
            int s = (slot < CAP) ? slot : -1;
            if (idx < Tn) g_s0[t] = s; else g_s1[t] = s;
            if (s >= 0) g_tok[e * CAP + s] = t;
        }
        base += __popc(bal);
    }
    int cnt = min(base, CAP);
    if (lane == 0) g_count[e] = cnt;
    for (int s = cnt + lane; s < CAP; s += 32) g_tok[e * CAP + s] = -1;
}

// ---------------- HMMA GEMM: 128x128 tile, ldmatrix fragment feed -----------
template <bool IS_G1>
__global__ void __launch_bounds__(256) moe_mma_kernel(const float* __restrict__ xin,
                                                      const float* __restrict__ w) {
    constexpr int KTOT = IS_G1 ? Dm : Hm;
    constexpr int NDIM = IS_G1 ? Hm : Dm;
    constexpr int NCH  = KTOT / 32;

    const int e = blockIdx.z;
    const int row0 = blockIdx.y * 128;
    if (row0 >= g_count[e]) return;
    const int nb = blockIdx.x * 128;

    __shared__ __align__(16) __nv_bfloat16 smh[SMH];
    const u32 sb = smem_u32(smh);
    const int tid = threadIdx.x;

    // ---- producer addressing (as in passing R8) ----
    const int arow = tid >> 1, kq = (tid & 1) * 16;     // A: 2 thr/row
    const int bkrow = tid >> 3, bng = tid & 7;          // B: 8 thr/k-row
    const float* aPtr;
    bool avalid = true;
    if (IS_G1) {
        int tok = g_tok[e * CAP + row0 + arow];
        avalid = (tok >= 0);
        aPtr = xin + (size_t)(avalid ? tok : 0) * Dm;
    } else {
        aPtr = g_h + (size_t)(e * CAP + row0 + arow) * Hm;
    }
    const float* wPtr = w + (size_t)e * KTOT * NDIM + (size_t)bkrow * NDIM + nb + bng * 16;

    float4 av[4], bv[4];
    #define LOADC(c) do {                                                     \
        const float* pa_ = aPtr + (size_t)(c) * 32 + kq;                      \
        const float* pb_ = wPtr + (size_t)(c) * 32 * NDIM;                    \
        _Pragma("unroll")                                                     \
        for (int j_ = 0; j_ < 4; j_++) {                                      \
            av[j_] = avalid ? *(const float4*)(pa_ + j_ * 4)                  \
                            : make_float4(0.f, 0.f, 0.f, 0.f);                \
            bv[j_] = *(const float4*)(pb_ + j_ * 4);                          \
        }                                                                     \
    } while (0)

    #define STOREC() do {                                                     \
        _Pragma("unroll")                                                     \
        for (int j_ = 0; j_ < 4; j_++) {                                      \
            float f0 = av[j_].x, f1 = av[j_].y, f2 = av[j_].z, f3 = av[j_].w; \
            __nv_bfloat16 h0 = __float2bfloat16(f0), h1 = __float2bfloat16(f1); \
            __nv_bfloat16 h2 = __float2bfloat16(f2), h3 = __float2bfloat16(f3); \
            __nv_bfloat16 l0 = __float2bfloat16(f0 - __bfloat162float(h0));   \
            __nv_bfloat16 l1 = __float2bfloat16(f1 - __bfloat162float(h1));   \
            __nv_bfloat16 l2 = __float2bfloat16(f2 - __bfloat162float(h2));   \
            __nv_bfloat16 l3 = __float2bfloat16(f3 - __bfloat162float(h3));   \
            int ia_ = arow * LDA + kq + j_ * 4;                               \
            *(u32*)&smh[AH_ + ia_]     = pack2bf(h0, h1);                     \
            *(u32*)&smh[AH_ + ia_ + 2] = pack2bf(h2, h3);                     \
            *(u32*)&smh[AL_ + ia_]     = pack2bf(l0, l1);                     \
            *(u32*)&smh[AL_ + ia_ + 2] = pack2bf(l2, l3);                     \
            f0 = bv[j_].x; f1 = bv[j_].y; f2 = bv[j_].z; f3 = bv[j_].w;       \
            h0 = __float2bfloat16(f0); h1 = __float2bfloat16(f1);             \
            h2 = __float2bfloat16(f2); h3 = __float2bfloat16(f3);             \
            l0 = __float2bfloat16(f0 - __bfloat162float(h0));                 \
            l1 = __float2bfloat16(f1 - __bfloat162float(h1));                 \
            l2 = __float2bfloat16(f2 - __bfloat162float(h2));                 \
            l3 = __float2bfloat16(f3 - __bfloat162float(h3));                 \
            int ib_ = bkrow * LDB + bng * 16 + j_ * 4;                        \
            *(u32*)&smh[BH_ + ib_]     = pack2bf(h0, h1);                     \
            *(u32*)&smh[BH_ + ib_ + 2] = pack2bf(h2, h3);                     \
            *(u32*)&smh[BL_ + ib_]     = pack2bf(l0, l1);                     \
            *(u32*)&smh[BL_ + ib_ + 2] = pack2bf(l2, l3);                     \
        }                                                                     \
    } while (0)

    // ---- consumer addressing ----
    const int lane = tid & 31, wid = tid >> 5;
    const int m0 = (wid >> 1) * 32, n0 = (wid & 1) * 64;
    const int g = lane >> 2;

    // ldmatrix lane->address components
    const int aRow = m0 + (lane & 15);                 // + mt*16
    const int aColq = (lane >> 4) * 8;                 // + ks*16
    const int bRowK = (lane & 7) + ((lane & 8) ? 8 : 0);  // + ks*16
    const int bColN = n0 + ((lane & 16) ? 8 : 0);         // + ntp*16

    float acc[2][8][4];
#pragma unroll
    for (int mt = 0; mt < 2; mt++)
#pragma unroll
        for (int nt = 0; nt < 8; nt++)
#pragma unroll
            for (int j = 0; j < 4; j++) acc[mt][nt][j] = 0.f;

    LOADC(0);
#pragma unroll 1
    for (int c = 0; c < NCH; c++) {
        __syncthreads();
        STOREC();
        __syncthreads();
        if (c + 1 < NCH) LOADC(c + 1);

#pragma unroll
        for (int ks = 0; ks < 2; ks++) {
            const int bk = ks * 16;
            u32 ah[2][4], al[2][4];
#pragma unroll
            for (int mt = 0; mt < 2; mt++) {
                const u32 aoff = (u32)((aRow + mt * 16) * LDA + bk + aColq);
                ldsm4(ah[mt], sb + (AH_ + aoff) * 2);
                ldsm4(al[mt], sb + (AL_ + aoff) * 2);
            }
#pragma unroll
            for (int ntp = 0; ntp < 4; ntp++) {
                const u32 boff = (u32)((bk + bRowK) * LDB + bColN + ntp * 16);
                u32 bh[4], bl[4];
                ldsm4t(bh, sb + (BH_ + boff) * 2);
                ldsm4t(bl, sb + (BL_ + boff) * 2);
                const int nt = 2 * ntp;
                mma16816(acc[0][nt],     ah[0], bh[0], bh[1]);
                mma16816(acc[1][nt],     ah[1], bh[0], bh[1]);
                mma16816(acc[0][nt + 1], ah[0], bh[2], bh[3]);
                mma16816(acc[1][nt + 1], ah[1], bh[2], bh[3]);
                mma16816(acc[0][nt],     al[0], bh[0], bh[1]);
                mma16816(acc[1][nt],     al[1], bh[0], bh[1]);
                mma16816(acc[0][nt + 1], al[0], bh[2], bh[3]);
                mma16816(acc[1][nt + 1], al[1], bh[2], bh[3]);
                mma16816(acc[0][nt],     ah[0], bl[0], bl[1]);
                mma16816(acc[1][nt],     ah[1], bl[0], bl[1]);
                mma16816(acc[0][nt + 1], ah[0], bl[2], bl[3]);
                mma16816(acc[1][nt + 1], ah[1], bl[2], bl[3]);
            }
        }
    }
    #undef LOADC
    #undef STOREC

    // ---- epilogue (verbatim from passing R8) ----
    const int tg = lane & 3;
#pragma unroll
    for (int mt = 0; mt < 2; mt++) {
        const int Rb = e * CAP + row0 + m0 + mt * 16 + g;    // rows Rb, Rb+8
#pragma unroll
        for (int nt = 0; nt < 8; nt++) {
            const int col = nb + n0 + nt * 8 + tg * 2;
            float v0 = acc[mt][nt][0], v1 = acc[mt][nt][1];
            float v2 = acc[mt][nt][2], v3 = acc[mt][nt][3];
            if (IS_G1) {
                v0 = 0.5f * v0 * (1.0f + erff(v0 * 0.70710678118654752440f));
                v1 = 0.5f * v1 * (1.0f + erff(v1 * 0.70710678118654752440f));
                v2 = 0.5f * v2 * (1.0f + erff(v2 * 0.70710678118654752440f));
                v3 = 0.5f * v3 * (1.0f + erff(v3 * 0.70710678118654752440f));
                *(float2*)(g_h + (size_t)Rb * Hm + col)       = make_float2(v0, v1);
                *(float2*)(g_h + (size_t)(Rb + 8) * Hm + col) = make_float2(v2, v3);
            } else {
                *(float2*)(g_eo + (size_t)Rb * Dm + col)       = make_float2(v0, v1);
                *(float2*)(g_eo + (size_t)(Rb + 8) * Dm + col) = make_float2(v2, v3);
            }
        }
    }
}

// ---------------- combine (verbatim, passing) ----------------
__global__ void combine_kernel(float* __restrict__ out) {
    int t = blockIdx.x;
    int c = threadIdx.x * 4;
    int e0 = g_e0[t], e1 = g_e1[t];
    int s0 = g_s0[t], s1 = g_s1[t];
    float w0 = g_w0[t], w1 = g_w1[t];
    float4 r = make_float4(0, 0, 0, 0);
    if (s0 >= 0) {
        float4 v = *(const float4*)(g_eo + (size_t)(e0 * CAP + s0) * Dm + c);
        r.x += w0 * v.x; r.y += w0 * v.y; r.z += w0 * v.z; r.w += w0 * v.w;
    }
    if (s1 >= 0) {
        float4 v = *(const float4*)(g_eo + (size_t)(e1 * CAP + s1) * Dm + c);
        r.x += w1 * v.x; r.y += w1 * v.y; r.z += w1 * v.z; r.w += w1 * v.w;
    }
    *(float4*)(out + (size_t)t * Dm + c) = r;
}

// ---------------- launch ----------------
extern "C" void kernel_launch(void* const* d_in, const int* in_sizes, int n_in,
                              void* d_out, int out_size) {
    const float* x     = (const float*)d_in[0];
    const float* wg    = (const float*)d_in[1];
    const float* cfc   = (const float*)d_in[2];
    const float* cproj = (const float*)d_in[3];
    float* out = (float*)d_out;

    router_kernel<<<Tn / 8, 256>>>(x, wg);
    assign_kernel<<<1, 256>>>();
    moe_mma_kernel<true><<<dim3(Hm / 128, CAP / 128, NE), 256>>>(x, cfc);
    moe_mma_kernel<false><<<dim3(Dm / 128, CAP / 128, NE), 256>>>(x, cproj);
    combine_kernel<<<Tn, 256>>>(out);
}

// round 12
// speedup vs baseline: 1.1564x; 1.1564x over previous
#include <cuda_runtime.h>
#include <cuda_bf16.h>
#include <math.h>
#include <stdint.h>

#define Tn   4096
#define Dm   1024
#define Hm   4096
#define NE   8
#define CAP  1280
#define LDA  24          // A smem row stride (halfs), 48B rows (16B mult)
#define LDB  136         // B smem row stride (halfs), 272B rows
// per-stage layout (halfs)
#define AH_  0
#define AL_  3072        // 128*24
#define BH_  6144
#define BL_  8320        // 6144 + 16*136
#define STGH 10496       // stage size in halfs (20992 B)
#define SMH  (2*STGH)    // 41984 B total

typedef unsigned int u32;
typedef unsigned short u16;

// ---------------- device scratch ----------------
__device__ int   g_e0[Tn], g_e1[Tn];
__device__ float g_w0[Tn], g_w1[Tn];
__device__ int   g_s0[Tn], g_s1[Tn];
__device__ int   g_tok[NE * CAP];
__device__ int   g_count[NE];
__device__ float g_h [(size_t)NE * CAP * Hm];
__device__ float g_eo[(size_t)NE * CAP * Dm];

// ---------------- helpers ----------------
__device__ __forceinline__ u32 smem_u32(const void* p) {
    u32 a;
    asm("{ .reg .u64 t; cvta.to.shared.u64 t, %1; cvt.u32.u64 %0, t; }" : "=r"(a) : "l"(p));
    return a;
}
__device__ __forceinline__ void ldsm4(u32* r, u32 a) {
    asm volatile("ldmatrix.sync.aligned.m8n8.x4.shared.b16 {%0,%1,%2,%3}, [%4];"
                 : "=r"(r[0]), "=r"(r[1]), "=r"(r[2]), "=r"(r[3]) : "r"(a));
}
__device__ __forceinline__ void ldsm4t(u32* r, u32 a) {
    asm volatile("ldmatrix.sync.aligned.m8n8.x4.trans.shared.b16 {%0,%1,%2,%3}, [%4];"
                 : "=r"(r[0]), "=r"(r[1]), "=r"(r[2]), "=r"(r[3]) : "r"(a));
}
__device__ __forceinline__ void mma16816(float* d, const u32* a, u32 b0, u32 b1) {
    asm volatile(
        "mma.sync.aligned.m16n8k16.row.col.f32.bf16.bf16.f32 "
        "{%0,%1,%2,%3}, {%4,%5,%6,%7}, {%8,%9}, {%0,%1,%2,%3};"
        : "+f"(d[0]), "+f"(d[1]), "+f"(d[2]), "+f"(d[3])
        : "r"(a[0]), "r"(a[1]), "r"(a[2]), "r"(a[3]), "r"(b0), "r"(b1));
}
__device__ __forceinline__ u32 pack2bf(__nv_bfloat16 a, __nv_bfloat16 b) {
    __nv_bfloat162 t; t.x = a; t.y = b;
    return *reinterpret_cast<u32*>(&t);
}

// ---------------- router (verbatim, passing) ----------------
__global__ void router_kernel(const float* __restrict__ x, const float* __restrict__ wg) {
    int warp = (blockIdx.x * blockDim.x + threadIdx.x) >> 5;
    int lane = threadIdx.x & 31;
    if (warp >= Tn) return;
    const float4* x4 = (const float4*)(x + (size_t)warp * Dm);
    float acc[NE];
#pragma unroll
    for (int e = 0; e < NE; e++) acc[e] = 0.f;
#pragma unroll
    for (int i = 0; i < Dm / 128; i++) {
        float4 v = x4[lane + i * 32];
        int k0 = (lane + i * 32) * 4;
#pragma unroll
        for (int j = 0; j < 4; j++) {
            float xv = (j == 0) ? v.x : (j == 1) ? v.y : (j == 2) ? v.z : v.w;
            float4 wA = *(const float4*)(wg + (size_t)(k0 + j) * NE);
            float4 wB = *(const float4*)(wg + (size_t)(k0 + j) * NE + 4);
            acc[0] += xv * wA.x; acc[1] += xv * wA.y; acc[2] += xv * wA.z; acc[3] += xv * wA.w;
            acc[4] += xv * wB.x; acc[5] += xv * wB.y; acc[6] += xv * wB.z; acc[7] += xv * wB.w;
        }
    }
#pragma unroll
    for (int off = 16; off; off >>= 1)
#pragma unroll
        for (int e = 0; e < NE; e++) acc[e] += __shfl_xor_sync(0xffffffffu, acc[e], off);
    if (lane == 0) {
        int b0 = 0; float v0 = acc[0];
        for (int e = 1; e < NE; e++) if (acc[e] > v0) { v0 = acc[e]; b0 = e; }
        int b1 = -1; float v1 = -INFINITY;
        for (int e = 0; e < NE; e++) if (e != b0 && acc[e] > v1) { v1 = acc[e]; b1 = e; }
        float e1 = expf(v1 - v0);
        float inv = 1.0f / (1.0f + e1);
        g_e0[warp] = b0; g_e1[warp] = b1;
        g_w0[warp] = inv; g_w1[warp] = e1 * inv;
    }
}

// ---------------- assignment (verbatim, passing) ----------------
__global__ void assign_kernel() {
    int e = threadIdx.x >> 5, lane = threadIdx.x & 31;
    int base = 0;
    for (int i0 = 0; i0 < 2 * Tn; i0 += 32) {
        int idx = i0 + lane;
        int t = idx & (Tn - 1);
        int sel = (idx < Tn) ? g_e0[t] : g_e1[t];
        bool mine = (sel == e);
        unsigned bal = __ballot_sync(0xffffffffu, mine);
        int pre = __popc(bal & ((1u << lane) - 1u));
        if (mine) {
            int slot = base + pre;
            int s = (slot < CAP) ? slot : -1;
            if (idx < Tn) g_s0[t] = s; else g_s1[t] = s;
            if (s >= 0) g_tok[e * CAP + s] = t;
        }
        base += __popc(bal);
    }
    int cnt = min(base, CAP);
    if (lane == 0) g_count[e] = cnt;
    for (int s = cnt + lane; s < CAP; s += 32) g_tok[e * CAP + s] = -1;
}

// ---------------- HMMA GEMM: 128x128 tile, K16 chunks, double-buffered ------
template <bool IS_G1>
__global__ void __launch_bounds__(256) moe_mma_kernel(const float* __restrict__ xin,
                                                      const float* __restrict__ w) {
    constexpr int KTOT = IS_G1 ? Dm : Hm;
    constexpr int NDIM = IS_G1 ? Hm : Dm;
    constexpr int NCH  = KTOT / 16;

    const int e = blockIdx.z;
    const int row0 = blockIdx.y * 128;
    if (row0 >= g_count[e]) return;
    const int nb = blockIdx.x * 128;

    __shared__ __align__(16) __nv_bfloat16 smh[SMH];
    const u32 sb = smem_u32(smh);
    const int tid = threadIdx.x;

    // ---- producer addressing ----
    const int arow = tid >> 1, kq = (tid & 1) * 8;      // A: 2 thr/row, 8 floats each
    const int bkrow = tid >> 4, bng = tid & 15;         // B: 16 thr/k-row, 8 floats each
    const float* aPtr;
    bool avalid = true;
    if (IS_G1) {
        int tok = g_tok[e * CAP + row0 + arow];
        avalid = (tok >= 0);
        aPtr = xin + (size_t)(avalid ? tok : 0) * Dm;
    } else {
        aPtr = g_h + (size_t)(e * CAP + row0 + arow) * Hm;
    }
    const float* wPtr = w + (size_t)e * KTOT * NDIM + (size_t)bkrow * NDIM + nb + bng * 8;

    float4 av[2], bv[2];
    #define LOADC(c) do {                                                     \
        const float* pa_ = aPtr + (size_t)(c) * 16 + kq;                      \
        const float* pb_ = wPtr + (size_t)(c) * 16 * NDIM;                    \
        av[0] = avalid ? *(const float4*)(pa_)     : make_float4(0.f,0.f,0.f,0.f); \
        av[1] = avalid ? *(const float4*)(pa_ + 4) : make_float4(0.f,0.f,0.f,0.f); \
        bv[0] = *(const float4*)(pb_);                                        \
        bv[1] = *(const float4*)(pb_ + 4);                                    \
    } while (0)

    #define STOREC(stg) do {                                                  \
        __nv_bfloat16* sp_ = smh + (stg) * STGH;                              \
        _Pragma("unroll")                                                     \
        for (int j_ = 0; j_ < 2; j_++) {                                      \
            float f0 = av[j_].x, f1 = av[j_].y, f2 = av[j_].z, f3 = av[j_].w; \
            __nv_bfloat16 h0 = __float2bfloat16(f0), h1 = __float2bfloat16(f1); \
            __nv_bfloat16 h2 = __float2bfloat16(f2), h3 = __float2bfloat16(f3); \
            __nv_bfloat16 l0 = __float2bfloat16(f0 - __bfloat162float(h0));   \
            __nv_bfloat16 l1 = __float2bfloat16(f1 - __bfloat162float(h1));   \
            __nv_bfloat16 l2 = __float2bfloat16(f2 - __bfloat162float(h2));   \
            __nv_bfloat16 l3 = __float2bfloat16(f3 - __bfloat162float(h3));   \
            int ia_ = arow * LDA + kq + j_ * 4;                               \
            *(u32*)&sp_[AH_ + ia_]     = pack2bf(h0, h1);                     \
            *(u32*)&sp_[AH_ + ia_ + 2] = pack2bf(h2, h3);                     \
            *(u32*)&sp_[AL_ + ia_]     = pack2bf(l0, l1);                     \
            *(u32*)&sp_[AL_ + ia_ + 2] = pack2bf(l2, l3);                     \
            f0 = bv[j_].x; f1 = bv[j_].y; f2 = bv[j_].z; f3 = bv[j_].w;       \
            h0 = __float2bfloat16(f0); h1 = __float2bfloat16(f1);             \
            h2 = __float2bfloat16(f2); h3 = __float2bfloat16(f3);             \
            l0 = __float2bfloat16(f0 - __bfloat162float(h0));                 \
            l1 = __float2bfloat16(f1 - __bfloat162float(h1));                 \
            l2 = __float2bfloat16(f2 - __bfloat162float(h2));                 \
            l3 = __float2bfloat16(f3 - __bfloat162float(h3));                 \
            int ib_ = bkrow * LDB + bng * 8 + j_ * 4;                         \
            *(u32*)&sp_[BH_ + ib_]     = pack2bf(h0, h1);                     \
            *(u32*)&sp_[BH_ + ib_ + 2] = pack2bf(h2, h3);                     \
            *(u32*)&sp_[BL_ + ib_]     = pack2bf(l0, l1);                     \
            *(u32*)&sp_[BL_ + ib_ + 2] = pack2bf(l2, l3);                     \
        }                                                                     \
    } while (0)

    // ---- consumer addressing ----
    const int lane = tid & 31, wid = tid >> 5;
    const int m0 = (wid >> 1) * 32, n0 = (wid & 1) * 64;
    const int g = lane >> 2;

    const int aRow = m0 + (lane & 15);
    const int aColq = (lane >> 4) * 8;
    const int bRowK = lane & 15;
    const int bColN = n0 + ((lane & 16) ? 8 : 0);

    float acc[2][8][4];
#pragma unroll
    for (int mt = 0; mt < 2; mt++)
#pragma unroll
        for (int nt = 0; nt < 8; nt++)
#pragma unroll
            for (int j = 0; j < 4; j++) acc[mt][nt][j] = 0.f;

    LOADC(0);
    STOREC(0);
    LOADC(1);
    __syncthreads();

#pragma unroll 1
    for (int c = 0; c < NCH; c++) {
        if (c + 1 < NCH) STOREC((c + 1) & 1);        // regs hold chunk c+1
        if (c + 2 < NCH) LOADC(c + 2);
        const u32 stg = sb + ((c & 1) ? STGH * 2 : 0);

        u32 ah[2][4], al[2][4];
#pragma unroll
        for (int mt = 0; mt < 2; mt++) {
            const u32 aoff = (u32)((aRow + mt * 16) * LDA + aColq);
            ldsm4(ah[mt], stg + (AH_ + aoff) * 2);
            ldsm4(al[mt], stg + (AL_ + aoff) * 2);
        }
#pragma unroll
        for (int ntp = 0; ntp < 4; ntp++) {
            const u32 boff = (u32)(bRowK * LDB + bColN + ntp * 16);
            u32 bh[4], bl[4];
            ldsm4t(bh, stg + (BH_ + boff) * 2);
            ldsm4t(bl, stg + (BL_ + boff) * 2);
            const int nt = 2 * ntp;
            mma16816(acc[0][nt],     ah[0], bh[0], bh[1]);
            mma16816(acc[1][nt],     ah[1], bh[0], bh[1]);
            mma16816(acc[0][nt + 1], ah[0], bh[2], bh[3]);
            mma16816(acc[1][nt + 1], ah[1], bh[2], bh[3]);
            mma16816(acc[0][nt],     al[0], bh[0], bh[1]);
            mma16816(acc[1][nt],     al[1], bh[0], bh[1]);
            mma16816(acc[0][nt + 1], al[0], bh[2], bh[3]);
            mma16816(acc[1][nt + 1], al[1], bh[2], bh[3]);
            mma16816(acc[0][nt],     ah[0], bl[0], bl[1]);
            mma16816(acc[1][nt],     ah[1], bl[0], bl[1]);
            mma16816(acc[0][nt + 1], ah[0], bl[2], bl[3]);
            mma16816(acc[1][nt + 1], ah[1], bl[2], bl[3]);
        }
        __syncthreads();
    }
    #undef LOADC
    #undef STOREC

    // ---- epilogue (verbatim from passing R10) ----
    const int tg = lane & 3;
#pragma unroll
    for (int mt = 0; mt < 2; mt++) {
        const int Rb = e * CAP + row0 + m0 + mt * 16 + g;
#pragma unroll
        for (int nt = 0; nt < 8; nt++) {
            const int col = nb + n0 + nt * 8 + tg * 2;
            float v0 = acc[mt][nt][0], v1 = acc[mt][nt][1];
            float v2 = acc[mt][nt][2], v3 = acc[mt][nt][3];
            if (IS_G1) {
                v0 = 0.5f * v0 * (1.0f + erff(v0 * 0.70710678118654752440f));
                v1 = 0.5f * v1 * (1.0f + erff(v1 * 0.70710678118654752440f));
                v2 = 0.5f * v2 * (1.0f + erff(v2 * 0.70710678118654752440f));
                v3 = 0.5f * v3 * (1.0f + erff(v3 * 0.70710678118654752440f));
                *(float2*)(g_h + (size_t)Rb * Hm + col)       = make_float2(v0, v1);
                *(float2*)(g_h + (size_t)(Rb + 8) * Hm + col) = make_float2(v2, v3);
            } else {
                *(float2*)(g_eo + (size_t)Rb * Dm + col)       = make_float2(v0, v1);
                *(float2*)(g_eo + (size_t)(Rb + 8) * Dm + col) = make_float2(v2, v3);
            }
        }
    }
}

// ---------------- combine (verbatim, passing) ----------------
__global__ void combine_kernel(float* __restrict__ out) {
    int t = blockIdx.x;
    int c = threadIdx.x * 4;
    int e0 = g_e0[t], e1 = g_e1[t];
    int s0 = g_s0[t], s1 = g_s1[t];
    float w0 = g_w0[t], w1 = g_w1[t];
    float4 r = make_float4(0, 0, 0, 0);
    if (s0 >= 0) {
        float4 v = *(const float4*)(g_eo + (size_t)(e0 * CAP + s0) * Dm + c);
        r.x += w0 * v.x; r.y += w0 * v.y; r.z += w0 * v.z; r.w += w0 * v.w;
    }
    if (s1 >= 0) {
        float4 v = *(const float4*)(g_eo + (size_t)(e1 * CAP + s1) * Dm + c);
        r.x += w1 * v.x; r.y += w1 * v.y; r.z += w1 * v.z; r.w += w1 * v.w;
    }
    *(float4*)(out + (size_t)t * Dm + c) = r;
}

// ---------------- launch ----------------
extern "C" void kernel_launch(void* const* d_in, const int* in_sizes, int n_in,
                              void* d_out, int out_size) {
    const float* x     = (const float*)d_in[0];
    const float* wg    = (const float*)d_in[1];
    const float* cfc   = (const float*)d_in[2];
    const float* cproj = (const float*)d_in[3];
    float* out = (float*)d_out;

    router_kernel<<<Tn / 8, 256>>>(x, wg);
    assign_kernel<<<1, 256>>>();
    moe_mma_kernel<true><<<dim3(Hm / 128, CAP / 128, NE), 256>>>(x, cfc);
    moe_mma_kernel<false><<<dim3(Dm / 128, CAP / 128, NE), 256>>>(x, cproj);
    combine_kernel<<<Tn, 256>>>(out);
}

// round 13
// speedup vs baseline: 1.2003x; 1.0380x over previous
#include <cuda_runtime.h>
#include <cuda_bf16.h>
#include <math.h>
#include <stdint.h>

#define Tn   4096
#define Dm   1024
#define Hm   4096
#define NE   8
#define CAP  1280
#define LDA  24          // A smem row stride (halfs), 48B rows
#define LDB  136         // B smem row stride (halfs), 272B rows
// per-stage layout (halfs)
#define AH_  0
#define AL_  3072        // 128*24
#define BH_  6144
#define BL_  8320        // 6144 + 16*136
#define STGH 10496       // stage size in halfs (20992 B)
#define SMH  (2*STGH)    // 41984 B total

typedef unsigned int u32;
typedef unsigned short u16;

// ---------------- device scratch ----------------
__device__ int   g_e0[Tn], g_e1[Tn];
__device__ float g_w0[Tn], g_w1[Tn];
__device__ int   g_s0[Tn], g_s1[Tn];
__device__ int   g_tok[NE * CAP];
__device__ int   g_count[NE];
__device__ float g_h [(size_t)NE * CAP * Hm];
__device__ float g_eo[(size_t)NE * CAP * Dm];

// ---------------- helpers ----------------
__device__ __forceinline__ u32 smem_u32(const void* p) {
    u32 a;
    asm("{ .reg .u64 t; cvta.to.shared.u64 t, %1; cvt.u32.u64 %0, t; }" : "=r"(a) : "l"(p));
    return a;
}
__device__ __forceinline__ void ldsm4(u32* r, u32 a) {
    asm volatile("ldmatrix.sync.aligned.m8n8.x4.shared.b16 {%0,%1,%2,%3}, [%4];"
                 : "=r"(r[0]), "=r"(r[1]), "=r"(r[2]), "=r"(r[3]) : "r"(a));
}
__device__ __forceinline__ void ldsm4t(u32* r, u32 a) {
    asm volatile("ldmatrix.sync.aligned.m8n8.x4.trans.shared.b16 {%0,%1,%2,%3}, [%4];"
                 : "=r"(r[0]), "=r"(r[1]), "=r"(r[2]), "=r"(r[3]) : "r"(a));
}
__device__ __forceinline__ void mma16816(float* d, const u32* a, u32 b0, u32 b1) {
    asm volatile(
        "mma.sync.aligned.m16n8k16.row.col.f32.bf16.bf16.f32 "
        "{%0,%1,%2,%3}, {%4,%5,%6,%7}, {%8,%9}, {%0,%1,%2,%3};"
        : "+f"(d[0]), "+f"(d[1]), "+f"(d[2]), "+f"(d[3])
        : "r"(a[0]), "r"(a[1]), "r"(a[2]), "r"(a[3]), "r"(b0), "r"(b1));
}
__device__ __forceinline__ u32 pack2bf(__nv_bfloat16 a, __nv_bfloat16 b) {
    __nv_bfloat162 t; t.x = a; t.y = b;
    return *reinterpret_cast<u32*>(&t);
}
// split float4 -> (hi pair0, hi pair1, lo pair0, lo pair1)
__device__ __forceinline__ void split4(float4 v, u32 &h01, u32 &h23, u32 &l01, u32 &l23) {
    __nv_bfloat16 h0 = __float2bfloat16(v.x), h1 = __float2bfloat16(v.y);
    __nv_bfloat16 h2 = __float2bfloat16(v.z), h3 = __float2bfloat16(v.w);
    __nv_bfloat16 l0 = __float2bfloat16(v.x - __bfloat162float(h0));
    __nv_bfloat16 l1 = __float2bfloat16(v.y - __bfloat162float(h1));
    __nv_bfloat16 l2 = __float2bfloat16(v.z - __bfloat162float(h2));
    __nv_bfloat16 l3 = __float2bfloat16(v.w - __bfloat162float(h3));
    h01 = pack2bf(h0, h1); h23 = pack2bf(h2, h3);
    l01 = pack2bf(l0, l1); l23 = pack2bf(l2, l3);
}

// ---------------- router (verbatim, passing) ----------------
__global__ void router_kernel(const float* __restrict__ x, const float* __restrict__ wg) {
    int warp = (blockIdx.x * blockDim.x + threadIdx.x) >> 5;
    int lane = threadIdx.x & 31;
    if (warp >= Tn) return;
    const float4* x4 = (const float4*)(x + (size_t)warp * Dm);
    float acc[NE];
#pragma unroll
    for (int e = 0; e < NE; e++) acc[e] = 0.f;
#pragma unroll
    for (int i = 0; i < Dm / 128; i++) {
        float4 v = x4[lane + i * 32];
        int k0 = (lane + i * 32) * 4;
#pragma unroll
        for (int j = 0; j < 4; j++) {
            float xv = (j == 0) ? v.x : (j == 1) ? v.y : (j == 2) ? v.z : v.w;
            float4 wA = *(const float4*)(wg + (size_t)(k0 + j) * NE);
            float4 wB = *(const float4*)(wg + (size_t)(k0 + j) * NE + 4);
            acc[0] += xv * wA.x; acc[1] += xv * wA.y; acc[2] += xv * wA.z; acc[3] += xv * wA.w;
            acc[4] += xv * wB.x; acc[5] += xv * wB.y; acc[6] += xv * wB.z; acc[7] += xv * wB.w;
        }
    }
#pragma unroll
    for (int off = 16; off; off >>= 1)
#pragma unroll
        for (int e = 0; e < NE; e++) acc[e] += __shfl_xor_sync(0xffffffffu, acc[e], off);
    if (lane == 0) {
        int b0 = 0; float v0 = acc[0];
        for (int e = 1; e < NE; e++) if (acc[e] > v0) { v0 = acc[e]; b0 = e; }
        int b1 = -1; float v1 = -INFINITY;
        for (int e = 0; e < NE; e++) if (e != b0 && acc[e] > v1) { v1 = acc[e]; b1 = e; }
        float e1 = expf(v1 - v0);
        float inv = 1.0f / (1.0f + e1);
        g_e0[warp] = b0; g_e1[warp] = b1;
        g_w0[warp] = inv; g_w1[warp] = e1 * inv;
    }
}

// ---------------- assignment (verbatim, passing) ----------------
__global__ void assign_kernel() {
    int e = threadIdx.x >> 5, lane = threadIdx.x & 31;
    int base = 0;
    for (int i0 = 0; i0 < 2 * Tn; i0 += 32) {
        int idx = i0 + lane;
        int t = idx & (Tn - 1);
        int sel = (idx < Tn) ? g_e0[t] : g_e1[t];
        bool mine = (sel == e);
        unsigned bal = __ballot_sync(0xffffffffu, mine);
        int pre = __popc(bal & ((1u << lane) - 1u));
        if (mine) {
            int slot = base + pre;
            int s = (slot < CAP) ? slot : -1;
            if (idx < Tn) g_s0[t] = s; else g_s1[t] = s;
            if (s >= 0) g_tok[e * CAP + s] = t;
        }
        base += __popc(bal);
    }
    int cnt = min(base, CAP);
    if (lane == 0) g_count[e] = cnt;
    for (int s = cnt + lane; s < CAP; s += 32) g_tok[e * CAP + s] = -1;
}

// ---------------- HMMA GEMM: 128x128 tile, K16 chunks, double-buffered ------
// STS packed as STS.128 (4 per thread per chunk).
template <bool IS_G1>
__global__ void __launch_bounds__(256, 2) moe_mma_kernel(const float* __restrict__ xin,
                                                         const float* __restrict__ w) {
    constexpr int KTOT = IS_G1 ? Dm : Hm;
    constexpr int NDIM = IS_G1 ? Hm : Dm;
    constexpr int NCH  = KTOT / 16;

    const int e = blockIdx.z;
    const int row0 = blockIdx.y * 128;
    if (row0 >= g_count[e]) return;
    const int nb = blockIdx.x * 128;

    __shared__ __align__(16) __nv_bfloat16 smh[SMH];
    const u32 sb = smem_u32(smh);
    const int tid = threadIdx.x;

    // ---- producer addressing ----
    const int arow = tid >> 1, kq = (tid & 1) * 8;      // A: 2 thr/row, 8 floats each
    const int bkrow = tid >> 4, bng = tid & 15;         // B: 16 thr/k-row, 8 floats each
    const float* aPtr;
    bool avalid = true;
    if (IS_G1) {
        int tok = g_tok[e * CAP + row0 + arow];
        avalid = (tok >= 0);
        aPtr = xin + (size_t)(avalid ? tok : 0) * Dm;
    } else {
        aPtr = g_h + (size_t)(e * CAP + row0 + arow) * Hm;
    }
    const float* wPtr = w + (size_t)e * KTOT * NDIM + (size_t)bkrow * NDIM + nb + bng * 8;

    const int iaW = arow * LDA + kq;            // halfs, 16B aligned
    const int ibW = bkrow * LDB + bng * 8;      // halfs, 16B aligned

    float4 av[2], bv[2];
    #define LOADC(c) do {                                                     \
        const float* pa_ = aPtr + (size_t)(c) * 16 + kq;                      \
        const float* pb_ = wPtr + (size_t)(c) * 16 * NDIM;                    \
        av[0] = avalid ? *(const float4*)(pa_)     : make_float4(0.f,0.f,0.f,0.f); \
        av[1] = avalid ? *(const float4*)(pa_ + 4) : make_float4(0.f,0.f,0.f,0.f); \
        bv[0] = *(const float4*)(pb_);                                        \
        bv[1] = *(const float4*)(pb_ + 4);                                    \
    } while (0)

    #define STOREC(stg) do {                                                  \
        __nv_bfloat16* sp_ = smh + (stg) * STGH;                              \
        u32 h0_, h1_, l0_, l1_, h2_, h3_, l2_, l3_;                           \
        split4(av[0], h0_, h1_, l0_, l1_);                                    \
        split4(av[1], h2_, h3_, l2_, l3_);                                    \
        *(uint4*)&sp_[AH_ + iaW] = make_uint4(h0_, h1_, h2_, h3_);            \
        *(uint4*)&sp_[AL_ + iaW] = make_uint4(l0_, l1_, l2_, l3_);            \
        split4(bv[0], h0_, h1_, l0_, l1_);                                    \
        split4(bv[1], h2_, h3_, l2_, l3_);                                    \
        *(uint4*)&sp_[BH_ + ibW] = make_uint4(h0_, h1_, h2_, h3_);            \
        *(uint4*)&sp_[BL_ + ibW] = make_uint4(l0_, l1_, l2_, l3_);            \
    } while (0)

    // ---- consumer addressing ----
    const int lane = tid & 31, wid = tid >> 5;
    const int m0 = (wid >> 1) * 32, n0 = (wid & 1) * 64;
    const int g = lane >> 2;

    const int aRow = m0 + (lane & 15);
    const int aColq = (lane >> 4) * 8;
    const int bRowK = lane & 15;
    const int bColN = n0 + ((lane & 16) ? 8 : 0);

    float acc[2][8][4];
#pragma unroll
    for (int mt = 0; mt < 2; mt++)
#pragma unroll
        for (int nt = 0; nt < 8; nt++)
#pragma unroll
            for (int j = 0; j < 4; j++) acc[mt][nt][j] = 0.f;

    LOADC(0);
    STOREC(0);
    LOADC(1);
    __syncthreads();

#pragma unroll 1
    for (int c = 0; c < NCH; c++) {
        if (c + 1 < NCH) STOREC((c + 1) & 1);        // regs hold chunk c+1
        if (c + 2 < NCH) LOADC(c + 2);
        const u32 stg = sb + ((c & 1) ? STGH * 2 : 0);

        u32 ah[2][4], al[2][4];
#pragma unroll
        for (int mt = 0; mt < 2; mt++) {
            const u32 aoff = (u32)((aRow + mt * 16) * LDA + aColq);
            ldsm4(ah[mt], stg + (AH_ + aoff) * 2);
            ldsm4(al[mt], stg + (AL_ + aoff) * 2);
        }
#pragma unroll
        for (int ntp = 0; ntp < 4; ntp++) {
            const u32 boff = (u32)(bRowK * LDB + bColN + ntp * 16);
            u32 bh[4], bl[4];
            ldsm4t(bh, stg + (BH_ + boff) * 2);
            ldsm4t(bl, stg + (BL_ + boff) * 2);
            const int nt = 2 * ntp;
            mma16816(acc[0][nt],     ah[0], bh[0], bh[1]);
            mma16816(acc[1][nt],     ah[1], bh[0], bh[1]);
            mma16816(acc[0][nt + 1], ah[0], bh[2], bh[3]);
            mma16816(acc[1][nt + 1], ah[1], bh[2], bh[3]);
            mma16816(acc[0][nt],     al[0], bh[0], bh[1]);
            mma16816(acc[1][nt],     al[1], bh[0], bh[1]);
            mma16816(acc[0][nt + 1], al[0], bh[2], bh[3]);
            mma16816(acc[1][nt + 1], al[1], bh[2], bh[3]);
            mma16816(acc[0][nt],     ah[0], bl[0], bl[1]);
            mma16816(acc[1][nt],     ah[1], bl[0], bl[1]);
            mma16816(acc[0][nt + 1], ah[0], bl[2], bl[3]);
            mma16816(acc[1][nt + 1], ah[1], bl[2], bl[3]);
        }
        __syncthreads();
    }
    #undef LOADC
    #undef STOREC

    // ---- epilogue (verbatim, passing) ----
    const int tg = lane & 3;
#pragma unroll
    for (int mt = 0; mt < 2; mt++) {
        const int Rb = e * CAP + row0 + m0 + mt * 16 + g;
#pragma unroll
        for (int nt = 0; nt < 8; nt++) {
            const int col = nb + n0 + nt * 8 + tg * 2;
            float v0 = acc[mt][nt][0], v1 = acc[mt][nt][1];
            float v2 = acc[mt][nt][2], v3 = acc[mt][nt][3];
            if (IS_G1) {
                v0 = 0.5f * v0 * (1.0f + erff(v0 * 0.70710678118654752440f));
                v1 = 0.5f * v1 * (1.0f + erff(v1 * 0.70710678118654752440f));
                v2 = 0.5f * v2 * (1.0f + erff(v2 * 0.70710678118654752440f));
                v3 = 0.5f * v3 * (1.0f + erff(v3 * 0.70710678118654752440f));
                *(float2*)(g_h + (size_t)Rb * Hm + col)       = make_float2(v0, v1);
                *(float2*)(g_h + (size_t)(Rb + 8) * Hm + col) = make_float2(v2, v3);
            } else {
                *(float2*)(g_eo + (size_t)Rb * Dm + col)       = make_float2(v0, v1);
                *(float2*)(g_eo + (size_t)(Rb + 8) * Dm + col) = make_float2(v2, v3);
            }
        }
    }
}

// ---------------- combine (verbatim, passing) ----------------
__global__ void combine_kernel(float* __restrict__ out) {
    int t = blockIdx.x;
    int c = threadIdx.x * 4;
    int e0 = g_e0[t], e1 = g_e1[t];
    int s0 = g_s0[t], s1 = g_s1[t];
    float w0 = g_w0[t], w1 = g_w1[t];
    float4 r = make_float4(0, 0, 0, 0);
    if (s0 >= 0) {
        float4 v = *(const float4*)(g_eo + (size_t)(e0 * CAP + s0) * Dm + c);
        r.x += w0 * v.x; r.y += w0 * v.y; r.z += w0 * v.z; r.w += w0 * v.w;
    }
    if (s1 >= 0) {
        float4 v = *(const float4*)(g_eo + (size_t)(e1 * CAP + s1) * Dm + c);
        r.x += w1 * v.x; r.y += w1 * v.y; r.z += w1 * v.z; r.w += w1 * v.w;
    }
    *(float4*)(out + (size_t)t * Dm + c) = r;
}

// ---------------- launch ----------------
extern "C" void kernel_launch(void* const* d_in, const int* in_sizes, int n_in,
                              void* d_out, int out_size) {
    const float* x     = (const float*)d_in[0];
    const float* wg    = (const float*)d_in[1];
    const float* cfc   = (const float*)d_in[2];
    const float* cproj = (const float*)d_in[3];
    float* out = (float*)d_out;

    router_kernel<<<Tn / 8, 256>>>(x, wg);
    assign_kernel<<<1, 256>>>();
    moe_mma_kernel<true><<<dim3(Hm / 128, CAP / 128, NE), 256>>>(x, cfc);
    moe_mma_kernel<false><<<dim3(Dm / 128, CAP / 128, NE), 256>>>(x, cproj);
    combine_kernel<<<Tn, 256>>>(out);
}

// round 14
// speedup vs baseline: 1.6039x; 1.3362x over previous
#include <cuda_runtime.h>
#include <cuda_fp16.h>
#include <math.h>
#include <stdint.h>

#define Tn   4096
#define Dm   1024
#define Hm   4096
#define NE   8
#define CAP  1280
#define LDA  40          // A smem row stride (halfs): 32 data + 8 pad (80B rows)
#define LDB  136         // B smem row stride (halfs): 128 data + 8 pad (272B rows)
// per-stage layout (halfs)
#define AH_  0
#define BH_  5120        // 128*40
#define STGH 9472        // 5120 + 32*136  (18944 B)
#define SMH  (2*STGH)    // 37888 B total

typedef unsigned int u32;
typedef unsigned short u16;

// ---------------- device scratch ----------------
__device__ int   g_e0[Tn], g_e1[Tn];
__device__ float g_w0[Tn], g_w1[Tn];
__device__ int   g_s0[Tn], g_s1[Tn];
__device__ int   g_tok[NE * CAP];
__device__ int   g_count[NE];
__device__ float g_h [(size_t)NE * CAP * Hm];
__device__ float g_eo[(size_t)NE * CAP * Dm];

// ---------------- helpers ----------------
__device__ __forceinline__ u32 smem_u32(const void* p) {
    u32 a;
    asm("{ .reg .u64 t; cvta.to.shared.u64 t, %1; cvt.u32.u64 %0, t; }" : "=r"(a) : "l"(p));
    return a;
}
__device__ __forceinline__ void ldsm4(u32* r, u32 a) {
    asm volatile("ldmatrix.sync.aligned.m8n8.x4.shared.b16 {%0,%1,%2,%3}, [%4];"
                 : "=r"(r[0]), "=r"(r[1]), "=r"(r[2]), "=r"(r[3]) : "r"(a));
}
__device__ __forceinline__ void ldsm4t(u32* r, u32 a) {
    asm volatile("ldmatrix.sync.aligned.m8n8.x4.trans.shared.b16 {%0,%1,%2,%3}, [%4];"
                 : "=r"(r[0]), "=r"(r[1]), "=r"(r[2]), "=r"(r[3]) : "r"(a));
}
__device__ __forceinline__ void mma16816(float* d, const u32* a, u32 b0, u32 b1) {
    asm volatile(
        "mma.sync.aligned.m16n8k16.row.col.f32.f16.f16.f32 "
        "{%0,%1,%2,%3}, {%4,%5,%6,%7}, {%8,%9}, {%0,%1,%2,%3};"
        : "+f"(d[0]), "+f"(d[1]), "+f"(d[2]), "+f"(d[3])
        : "r"(a[0]), "r"(a[1]), "r"(a[2]), "r"(a[3]), "r"(b0), "r"(b1));
}
__device__ __forceinline__ u32 packh2(float a, float b) {
    __half2 t = __floats2half2_rn(a, b);
    return *reinterpret_cast<u32*>(&t);
}

// ---------------- router (verbatim, passing) ----------------
__global__ void router_kernel(const float* __restrict__ x, const float* __restrict__ wg) {
    int warp = (blockIdx.x * blockDim.x + threadIdx.x) >> 5;
    int lane = threadIdx.x & 31;
    if (warp >= Tn) return;
    const float4* x4 = (const float4*)(x + (size_t)warp * Dm);
    float acc[NE];
#pragma unroll
    for (int e = 0; e < NE; e++) acc[e] = 0.f;
#pragma unroll
    for (int i = 0; i < Dm / 128; i++) {
        float4 v = x4[lane + i * 32];
        int k0 = (lane + i * 32) * 4;
#pragma unroll
        for (int j = 0; j < 4; j++) {
            float xv = (j == 0) ? v.x : (j == 1) ? v.y : (j == 2) ? v.z : v.w;
            float4 wA = *(const float4*)(wg + (size_t)(k0 + j) * NE);
            float4 wB = *(const float4*)(wg + (size_t)(k0 + j) * NE + 4);
            acc[0] += xv * wA.x; acc[1] += xv * wA.y; acc[2] += xv * wA.z; acc[3] += xv * wA.w;
            acc[4] += xv * wB.x; acc[5] += xv * wB.y; acc[6] += xv * wB.z; acc[7] += xv * wB.w;
        }
    }
#pragma unroll
    for (int off = 16; off; off >>= 1)
#pragma unroll
        for (int e = 0; e < NE; e++) acc[e] += __shfl_xor_sync(0xffffffffu, acc[e], off);
    if (lane == 0) {
        int b0 = 0; float v0 = acc[0];
        for (int e = 1; e < NE; e++) if (acc[e] > v0) { v0 = acc[e]; b0 = e; }
        int b1 = -1; float v1 = -INFINITY;
        for (int e = 0; e < NE; e++) if (e != b0 && acc[e] > v1) { v1 = acc[e]; b1 = e; }
        float e1 = expf(v1 - v0);
        float inv = 1.0f / (1.0f + e1);
        g_e0[warp] = b0; g_e1[warp] = b1;
        g_w0[warp] = inv; g_w1[warp] = e1 * inv;
    }
}

// ---------------- assignment (verbatim, passing) ----------------
__global__ void assign_kernel() {
    int e = threadIdx.x >> 5, lane = threadIdx.x & 31;
    int base = 0;
    for (int i0 = 0; i0 < 2 * Tn; i0 += 32) {
        int idx = i0 + lane;
        int t = idx & (Tn - 1);
        int sel = (idx < Tn) ? g_e0[t] : g_e1[t];
        bool mine = (sel == e);
        unsigned bal = __ballot_sync(0xffffffffu, mine);
        int pre = __popc(bal & ((1u << lane) - 1u));
        if (mine) {
            int slot = base + pre;
            int s = (slot < CAP) ? slot : -1;
            if (idx < Tn) g_s0[t] = s; else g_s1[t] = s;
            if (s >= 0) g_tok[e * CAP + s] = t;
        }
        base += __popc(bal);
    }
    int cnt = min(base, CAP);
    if (lane == 0) g_count[e] = cnt;
    for (int s = cnt + lane; s < CAP; s += 32) g_tok[e * CAP + s] = -1;
}

// ---------------- HMMA GEMM: 128x128 tile, fp16 single-pass, K32 chunks -----
template <bool IS_G1>
__global__ void __launch_bounds__(256, 2) moe_mma_kernel(const float* __restrict__ xin,
                                                         const float* __restrict__ w) {
    constexpr int KTOT = IS_G1 ? Dm : Hm;
    constexpr int NDIM = IS_G1 ? Hm : Dm;
    constexpr int NCH  = KTOT / 32;

    const int e = blockIdx.z;
    const int row0 = blockIdx.y * 128;
    if (row0 >= g_count[e]) return;
    const int nb = blockIdx.x * 128;

    __shared__ __align__(16) __half smh[SMH];
    const u32 sb = smem_u32(smh);
    const int tid = threadIdx.x;

    // ---- producer addressing ----
    const int arow = tid >> 1, kq = (tid & 1) * 16;     // A: 2 thr/row, 16 floats each
    const int bkrow = tid >> 3, bng = tid & 7;          // B: 8 thr/k-row, 16 floats each
    const float* aPtr;
    bool avalid = true;
    if (IS_G1) {
        int tok = g_tok[e * CAP + row0 + arow];
        avalid = (tok >= 0);
        aPtr = xin + (size_t)(avalid ? tok : 0) * Dm;
    } else {
        aPtr = g_h + (size_t)(e * CAP + row0 + arow) * Hm;
    }
    const float* wPtr = w + (size_t)e * KTOT * NDIM + (size_t)bkrow * NDIM + nb + bng * 16;

    const int iaW = arow * LDA + kq;            // halfs, 16B-aligned
    const int ibW = bkrow * LDB + bng * 16;     // halfs, 16B-aligned

    float4 av[4], bv[4];
    #define LOADC(c) do {                                                     \
        const float* pa_ = aPtr + (size_t)(c) * 32 + kq;                      \
        const float* pb_ = wPtr + (size_t)(c) * 32 * NDIM;                    \
        _Pragma("unroll")                                                     \
        for (int j_ = 0; j_ < 4; j_++) {                                      \
            av[j_] = avalid ? *(const float4*)(pa_ + j_ * 4)                  \
                            : make_float4(0.f, 0.f, 0.f, 0.f);                \
            bv[j_] = *(const float4*)(pb_ + j_ * 4);                          \
        }                                                                     \
    } while (0)

    #define STOREC(stg) do {                                                  \
        __half* sp_ = smh + (stg) * STGH;                                     \
        *(uint4*)&sp_[AH_ + iaW] = make_uint4(                                \
            packh2(av[0].x, av[0].y), packh2(av[0].z, av[0].w),               \
            packh2(av[1].x, av[1].y), packh2(av[1].z, av[1].w));              \
        *(uint4*)&sp_[AH_ + iaW + 8] = make_uint4(                            \
            packh2(av[2].x, av[2].y), packh2(av[2].z, av[2].w),               \
            packh2(av[3].x, av[3].y), packh2(av[3].z, av[3].w));              \
        *(uint4*)&sp_[BH_ + ibW] = make_uint4(                                \
            packh2(bv[0].x, bv[0].y), packh2(bv[0].z, bv[0].w),               \
            packh2(bv[1].x, bv[1].y), packh2(bv[1].z, bv[1].w));              \
        *(uint4*)&sp_[BH_ + ibW + 8] = make_uint4(                            \
            packh2(bv[2].x, bv[2].y), packh2(bv[2].z, bv[2].w),               \
            packh2(bv[3].x, bv[3].y), packh2(bv[3].z, bv[3].w));              \
    } while (0)

    // ---- consumer addressing ----
    const int lane = tid & 31, wid = tid >> 5;
    const int m0 = (wid >> 1) * 32, n0 = (wid & 1) * 64;
    const int g = lane >> 2;

    const int aRow = m0 + (lane & 15);
    const int aColq = (lane >> 4) * 8;                 // + ks*16
    const int bRowK = lane & 15;                       // + ks*16
    const int bColN = n0 + ((lane & 16) ? 8 : 0);      // + ntp*16

    float acc[2][8][4];
#pragma unroll
    for (int mt = 0; mt < 2; mt++)
#pragma unroll
        for (int nt = 0; nt < 8; nt++)
#pragma unroll
            for (int j = 0; j < 4; j++) acc[mt][nt][j] = 0.f;

    LOADC(0);
    STOREC(0);
    LOADC(1);
    __syncthreads();

#pragma unroll 1
    for (int c = 0; c < NCH; c++) {
        if (c + 1 < NCH) STOREC((c + 1) & 1);        // regs hold chunk c+1
        if (c + 2 < NCH) LOADC(c + 2);
        const u32 stg = sb + ((c & 1) ? STGH * 2 : 0);

#pragma unroll
        for (int ks = 0; ks < 2; ks++) {
            u32 ah[2][4];
#pragma unroll
            for (int mt = 0; mt < 2; mt++) {
                const u32 aoff = (u32)((aRow + mt * 16) * LDA + ks * 16 + aColq);
                ldsm4(ah[mt], stg + (AH_ + aoff) * 2);
            }
#pragma unroll
            for (int ntp = 0; ntp < 4; ntp++) {
                const u32 boff = (u32)((ks * 16 + bRowK) * LDB + bColN + ntp * 16);
                u32 bf[4];
                ldsm4t(bf, stg + (BH_ + boff) * 2);
                const int nt = 2 * ntp;
                mma16816(acc[0][nt],     ah[0], bf[0], bf[1]);
                mma16816(acc[1][nt],     ah[1], bf[0], bf[1]);
                mma16816(acc[0][nt + 1], ah[0], bf[2], bf[3]);
                mma16816(acc[1][nt + 1], ah[1], bf[2], bf[3]);
            }
        }
        __syncthreads();
    }
    #undef LOADC
    #undef STOREC

    // ---- epilogue (verbatim, passing) ----
    const int tg = lane & 3;
#pragma unroll
    for (int mt = 0; mt < 2; mt++) {
        const int Rb = e * CAP + row0 + m0 + mt * 16 + g;
#pragma unroll
        for (int nt = 0; nt < 8; nt++) {
            const int col = nb + n0 + nt * 8 + tg * 2;
            float v0 = acc[mt][nt][0], v1 = acc[mt][nt][1];
            float v2 = acc[mt][nt][2], v3 = acc[mt][nt][3];
            if (IS_G1) {
                v0 = 0.5f * v0 * (1.0f + erff(v0 * 0.70710678118654752440f));
                v1 = 0.5f * v1 * (1.0f + erff(v1 * 0.70710678118654752440f));
                v2 = 0.5f * v2 * (1.0f + erff(v2 * 0.70710678118654752440f));
                v3 = 0.5f * v3 * (1.0f + erff(v3 * 0.70710678118654752440f));
                *(float2*)(g_h + (size_t)Rb * Hm + col)       = make_float2(v0, v1);
                *(float2*)(g_h + (size_t)(Rb + 8) * Hm + col) = make_float2(v2, v3);
            } else {
                *(float2*)(g_eo + (size_t)Rb * Dm + col)       = make_float2(v0, v1);
                *(float2*)(g_eo + (size_t)(Rb + 8) * Dm + col) = make_float2(v2, v3);
            }
        }
    }
}

// ---------------- combine (verbatim, passing) ----------------
__global__ void combine_kernel(float* __restrict__ out) {
    int t = blockIdx.x;
    int c = threadIdx.x * 4;
    int e0 = g_e0[t], e1 = g_e1[t];
    int s0 = g_s0[t], s1 = g_s1[t];
    float w0 = g_w0[t], w1 = g_w1[t];
    float4 r = make_float4(0, 0, 0, 0);
    if (s0 >= 0) {
        float4 v = *(const float4*)(g_eo + (size_t)(e0 * CAP + s0) * Dm + c);
        r.x += w0 * v.x; r.y += w0 * v.y; r.z += w0 * v.z; r.w += w0 * v.w;
    }
    if (s1 >= 0) {
        float4 v = *(const float4*)(g_eo + (size_t)(e1 * CAP + s1) * Dm + c);
        r.x += w1 * v.x; r.y += w1 * v.y; r.z += w1 * v.z; r.w += w1 * v.w;
    }
    *(float4*)(out + (size_t)t * Dm + c) = r;
}

// ---------------- launch ----------------
extern "C" void kernel_launch(void* const* d_in, const int* in_sizes, int n_in,
                              void* d_out, int out_size) {
    const float* x     = (const float*)d_in[0];
    const float* wg    = (const float*)d_in[1];
    const float* cfc   = (const float*)d_in[2];
    const float* cproj = (const float*)d_in[3];
    float* out = (float*)d_out;

    router_kernel<<<Tn / 8, 256>>>(x, wg);
    assign_kernel<<<1, 256>>>();
    moe_mma_kernel<true><<<dim3(Hm / 128, CAP / 128, NE), 256>>>(x, cfc);
    moe_mma_kernel<false><<<dim3(Dm / 128, CAP / 128, NE), 256>>>(x, cproj);
    combine_kernel<<<Tn, 256>>>(out);
}